// round 1
// baseline (speedup 1.0000x reference)
#include <cuda_runtime.h>

// Problem constants (fixed by the reference)
#define BB   4
#define CC   256
#define HH   128
#define WW   256
#define NGRP 4
#define CG   64      // channels per group
#define WIN  9       // window taps (1 x 9)
#define CK   32      // channel chunk held in smem

__global__ __launch_bounds__(256)
void crestereo_corr_kernel(const float* __restrict__ left,
                           const float* __restrict__ right,
                           const float* __restrict__ flow,
                           float* __restrict__ out)
{
    __shared__ float srw[CK][WW];   // warped right row for current channel chunk

    const int bh = blockIdx.x;
    const int b  = bh / HH;
    const int h  = bh % HH;
    const int w  = threadIdx.x;
    const int HW = HH * WW;

    // ---- per-pixel bilinear setup (invariant across channels) ----
    const float fx = flow[(((size_t)b * 2 + 0) * HH + h) * WW + w];
    const float fy = flow[(((size_t)b * 2 + 1) * HH + h) * WW + w];
    const float x = (float)w + fx;
    const float y = (float)h + fy;
    const float x0f = floorf(x);
    const float y0f = floorf(y);
    const int ix0 = (int)x0f;
    const int iy0 = (int)y0f;
    const float ax = x - x0f;
    const float ay = y - y0f;

    float w00 = (1.f - ax) * (1.f - ay);
    float w01 = ax * (1.f - ay);
    float w10 = (1.f - ax) * ay;
    float w11 = ax * ay;

    // zero-padding validity + clamped gather offsets
    const int x0c = min(max(ix0, 0), WW - 1);
    const int x1c = min(max(ix0 + 1, 0), WW - 1);
    const int y0c = min(max(iy0, 0), HH - 1);
    const int y1c = min(max(iy0 + 1, 0), HH - 1);
    if (!(ix0     >= 0 && ix0     <= WW - 1 && iy0     >= 0 && iy0     <= HH - 1)) w00 = 0.f;
    if (!(ix0 + 1 >= 0 && ix0 + 1 <= WW - 1 && iy0     >= 0 && iy0     <= HH - 1)) w01 = 0.f;
    if (!(ix0     >= 0 && ix0     <= WW - 1 && iy0 + 1 >= 0 && iy0 + 1 <= HH - 1)) w10 = 0.f;
    if (!(ix0 + 1 >= 0 && ix0 + 1 <= WW - 1 && iy0 + 1 >= 0 && iy0 + 1 <= HH - 1)) w11 = 0.f;

    const int o00 = y0c * WW + x0c;
    const int o01 = y0c * WW + x1c;
    const int o10 = y1c * WW + x0c;
    const int o11 = y1c * WW + x1c;

    // 9 replicate-clamped sliding-window indices (applied to the WARPED row)
    int widx[WIN];
#pragma unroll
    for (int k = 0; k < WIN; ++k)
        widx[k] = min(max(w + k - 4, 0), WW - 1);

    const float* lbase = left  + (size_t)b * CC * HW + (size_t)h * WW + w;
    const float* rbase = right + (size_t)b * CC * HW;

    float acc[WIN];

    for (int g = 0; g < NGRP; ++g) {
#pragma unroll
        for (int k = 0; k < WIN; ++k) acc[k] = 0.f;

        for (int ch0 = g * CG; ch0 < (g + 1) * CG; ch0 += CK) {
            __syncthreads();   // protect previous chunk's readers

            // phase 1: bilinear warp CK channels of this row into smem
#pragma unroll
            for (int cc = 0; cc < CK; ++cc) {
                const float* rb = rbase + (size_t)(ch0 + cc) * HW;
                float v = rb[o00] * w00 + rb[o01] * w01
                        + rb[o10] * w10 + rb[o11] * w11;
                srw[cc][w] = v;
            }
            __syncthreads();

            // phase 2: sliding-window correlation accumulate
#pragma unroll
            for (int cc = 0; cc < CK; ++cc) {
                const float lv = lbase[(size_t)(ch0 + cc) * HW];
#pragma unroll
                for (int k = 0; k < WIN; ++k)
                    acc[k] += lv * srw[cc][widx[k]];
            }
        }

        // write 9 output taps for this group (coalesced across w)
        const float scale = 1.f / (float)CG;
#pragma unroll
        for (int k = 0; k < WIN; ++k)
            out[((((size_t)b * (NGRP * WIN)) + g * WIN + k) * HH + h) * WW + w]
                = acc[k] * scale;
    }
}

extern "C" void kernel_launch(void* const* d_in, const int* in_sizes, int n_in,
                              void* d_out, int out_size)
{
    const float* left  = (const float*)d_in[0];
    const float* right = (const float*)d_in[1];
    const float* flow  = (const float*)d_in[2];
    float* out = (float*)d_out;

    dim3 grid(BB * HH);   // 512 blocks, one per (b, h) row
    dim3 block(WW);       // 256 threads, one per w
    crestereo_corr_kernel<<<grid, block>>>(left, right, flow, out);
}